// round 6
// baseline (speedup 1.0000x reference)
#include <cuda_runtime.h>
#include <cuda_bf16.h>

// ---------------------------------------------------------------------------
// FHN_LSTM: iterated two-layer "LSTM-from-zero" map.
//   B=64 batch, H=512 hidden, T=1000 steps.
//   Live gates only: i, g, o (f-gate and W_hh are dead since h0=c0=0).
//   h_next[d] = sig(o_d) * tanh( sig(i_d) * tanh(g_d) ),  gates = h @ W_ih.T + (b_ih+b_hh)
//   Outputs per step: u[b] = h.W_u + b_u, w[b] = h.W_w + b_w  -> out[64000]+[64000]
//
// Persistent kernel: 128 CTAs x 256 threads, each CTA owns 4 h-dims, weights
// SMEM-resident. Grid barrier between layers (monotone ticket counter).
// Bitwise fixed-point early exit: once the carry h repeats exactly, all future
// outputs are identical -> bulk-fill and quit (provably output-identical).
// ---------------------------------------------------------------------------

#define NCTA   128
#define NTH    256
#define BB     64      // batch
#define HH     512     // hidden
#define TT     1000    // time steps
#define KP     256     // k-pairs (HH/2)
#define ROWS   12      // 3 gates * 4 dims per CTA per layer

// SMEM layout (floats)
#define SW_OFF    0                       // [2][12][512] weights
#define SW_SZ     (2 * ROWS * HH)         // 12288
#define PART_OFF  (SW_OFF + SW_SZ)        // [12][8][64] partials
#define PART_SZ   (ROWS * 8 * BB)         // 6144
#define WV_OFF    (PART_OFF + PART_SZ)    // [512] output weight vector
#define WV_SZ     HH
#define BIAS_OFF  (WV_OFF + WV_SZ)        // [24] gate biases
#define BIAS_SZ   (2 * ROWS)
#define SMEM_FLOATS (BIAS_OFF + BIAS_SZ)
#define SMEM_BYTES  (SMEM_FLOATS * 4)

// Ping-pong h buffers. Layout: [kp][b] float2 = (h[2kp][b], h[2kp+1][b]).
__device__ __align__(16) float2 g_h[2][KP * BB];
__device__ unsigned g_bar;       // monotone ticket; 2^32 % NCTA == 0 -> wrap-safe
__device__ unsigned g_chg[2];    // parity-indexed "carry changed this step" flags

typedef unsigned long long ull;

__device__ __forceinline__ void ffma2(ull& d, ull a, ull b) {
    // packed 2x fp32 fma: d.lo += a.lo*b.lo ; d.hi += a.hi*b.hi
    asm("fma.rn.f32x2 %0, %1, %2, %0;" : "+l"(d) : "l"(a), "l"(b));
}
__device__ __forceinline__ float fold2(ull v) {
    return __uint_as_float((unsigned)v) + __uint_as_float((unsigned)(v >> 32));
}
__device__ __forceinline__ float sig_(float x) {
    return 1.0f / (1.0f + __expf(-x));
}
__device__ __forceinline__ float tanh_(float x) {
    // exact at the limits: __expf(2x)->inf => 1 ; ->0 => -1
    return 1.0f - __fdividef(2.0f, __expf(2.0f * x) + 1.0f);
}

// Grid barrier. __threadfence() is gpu scope (>= cluster) so ptxas emits
// CCTL.IVALL, invalidating stale L1 lines of peer-written h buffers.
__device__ __forceinline__ void gbar(int tid) {
    __syncthreads();
    if (tid == 0) {
        __threadfence();
        unsigned pos    = atomicAdd(&g_bar, 1u);
        unsigned target = (pos - (pos & (NCTA - 1u))) + NCTA;
        while ((int)(*(volatile unsigned*)&g_bar - target) < 0) { }
        __threadfence();
    }
    __syncthreads();
}

// One dense layer for this CTA's 4 dims, all 64 batches.
// Thread map (GEMM phase): kg = tid>>5 (warp = k-group of 64 k), bq = tid&31
// (lane = batch pair 2bq, 2bq+1).
// If DETECT: compare new h vs old (bitwise) and OR the block result into
// g_chg[par].
template <bool DETECT>
__device__ __forceinline__ void do_layer(
    int l, const float2* __restrict__ inbuf, float2* __restrict__ outbuf,
    const float* sw, float* part, const float* sbias, int cta, int tid, int par)
{
    const int kg = tid >> 5;
    const int bq = tid & 31;

    ull acc[ROWS][2];
#pragma unroll
    for (int r = 0; r < ROWS; r++) { acc[r][0] = 0ull; acc[r][1] = 0ull; }

    // h pairs: (ulonglong2*)inbuf has 32 elements per kp row; element bq holds
    // packed (even-k, odd-k) h for batches 2bq and 2bq+1.
    const ulonglong2* hp = (const ulonglong2*)inbuf + bq;
    const float*      wl = sw + l * (ROWS * HH);
    const int kp0 = kg * 32;

#pragma unroll 4
    for (int s = 0; s < 32; s++) {
        const int kp = kp0 + s;
        ulonglong2 hv = hp[(size_t)kp * 32];
#pragma unroll
        for (int r = 0; r < ROWS; r++) {
            ull w = *(const ull*)(wl + r * HH + 2 * kp);   // warp-uniform LDS.64
            ffma2(acc[r][0], w, hv.x);
            ffma2(acc[r][1], w, hv.y);
        }
    }

    // partials -> SMEM [row][kg][b] (float2 store over batch pair: conflict-free)
    float2* p2 = (float2*)part;
#pragma unroll
    for (int r = 0; r < ROWS; r++) {
        p2[(r * 8 + kg) * 32 + bq] = make_float2(fold2(acc[r][0]), fold2(acc[r][1]));
    }
    __syncthreads();

    // reduce over kg + activations. Thread (j = tid>>6, b = tid&63).
    const int j = tid >> 6;
    const int b = tid & 63;
    float g3[3];
#pragma unroll
    for (int r = 0; r < 3; r++) {
        const int row = r * 4 + j;
        float s = sbias[l * ROWS + row];
#pragma unroll
        for (int k2 = 0; k2 < 8; k2++) s += part[(row * 8 + k2) * BB + b];
        g3[r] = s;
    }
    const float c  = sig_(g3[0]) * tanh_(g3[1]);
    const float h  = sig_(g3[2]) * tanh_(c);

    const int d    = 4 * cta + j;
    const int comp = d & 1;                 // even/odd slot of the float2 pair
    float* po = (float*)&outbuf[(d >> 1) * BB + b];
    if (DETECT) {
        const float old = po[comp];
        po[comp] = h;
        int ch  = (__float_as_uint(old) != __float_as_uint(h));
        int any = __syncthreads_or(ch);
        if (any && tid == 0) atomicOr(&g_chg[par], 1u);
    } else {
        po[comp] = h;
    }
}

// Output projection: one length-512 dot per CTA (u for cta<64, w else), by
// warp 0 reading the carry buffer. Butterfly reduce -> ALL lanes hold the sum.
__device__ __forceinline__ float outdot_val(
    const float2* __restrict__ hA, const float* wvec, float bias,
    int bo, int lane)
{
    float acc = 0.0f;
    const float2* wv2 = (const float2*)wvec;
#pragma unroll
    for (int m = 0; m < 8; m++) {
        const int kp = lane + 32 * m;
        float2 w2 = wv2[kp];
        float2 h2 = hA[kp * BB + bo];
        acc += w2.x * h2.x + w2.y * h2.y;
    }
#pragma unroll
    for (int off = 16; off > 0; off >>= 1)
        acc += __shfl_xor_sync(0xffffffffu, acc, off);
    return acc + bias;
}

__global__ void __launch_bounds__(NTH, 1) fhn_lstm_kernel(
    const float* __restrict__ u0,   const float* __restrict__ w0,
    const float* __restrict__ Kc,   const float* __restrict__ W_in,
    const float* __restrict__ b_in,
    const float* __restrict__ Wih0, const float* __restrict__ bih0,
    const float* __restrict__ bhh0,
    const float* __restrict__ Wih1, const float* __restrict__ bih1,
    const float* __restrict__ bhh1,
    const float* __restrict__ Wu,   const float* __restrict__ bu,
    const float* __restrict__ Ww,   const float* __restrict__ bw,
    float* __restrict__ out)
{
    extern __shared__ float smem[];
    float* sw    = smem + SW_OFF;
    float* part  = smem + PART_OFF;
    float* wvec  = smem + WV_OFF;
    float* sbias = smem + BIAS_OFF;

    const int cta = blockIdx.x;
    const int tid = threadIdx.x;

    // ---- init: weights (rows i,g,o of this CTA's 4 dims, both layers) -> SMEM
    // gate row base in pytorch [4H, H] layout: i=0, f=1(dead), g=2, o=3
    for (int idx = tid; idx < 2 * ROWS * HH; idx += NTH) {
        const int row = idx >> 9;          // 0..23
        const int k   = idx & (HH - 1);
        const int l   = row >= ROWS;
        const int rr  = row - l * ROWS;    // 0..11
        const int r   = rr >> 2;           // gate index 0..2
        const int j   = rr & 3;            // local dim
        const int gate = (r == 0) ? 0 : (r == 1) ? 2 : 3;
        const float* Wih = l ? Wih1 : Wih0;
        sw[idx] = Wih[(size_t)(gate * HH + 4 * cta + j) * HH + k];
    }
    if (tid < 2 * ROWS) {
        const int row = tid;
        const int l   = row >= ROWS;
        const int rr  = row - l * ROWS;
        const int r   = rr >> 2;
        const int j   = rr & 3;
        const int gate = (r == 0) ? 0 : (r == 1) ? 2 : 3;
        const int src  = gate * HH + 4 * cta + j;
        sbias[row] = (l ? bih1[src] : bih0[src]) + (l ? bhh1[src] : bhh0[src]);
    }
    {
        const float* wv = (cta < BB) ? Wu : Ww;
        for (int i = tid; i < HH; i += NTH) wvec[i] = wv[i];
    }
    const float obias  = (cta < BB) ? bu[0] : bw[0];
    const int   bo     = cta & (BB - 1);
    const long long obase = (long long)((cta < BB) ? 0 : BB * TT) + (long long)bo * TT;

    // ---- prologue: x = [u0,w0,K] @ W_in.T + b_in  -> carry buffer g_h[0]
    {
        const int j = tid >> 6;
        const int b = tid & 63;
        const int d = 4 * cta + j;
        const float x = W_in[d * 3 + 0] * u0[b] + W_in[d * 3 + 1] * w0[b]
                      + W_in[d * 3 + 2] * Kc[b] + b_in[d];
        float* po = (float*)&g_h[0][(d >> 1) * BB + b];
        po[d & 1] = x;
    }
    if (tid == 0) { g_chg[0] = 0u; g_chg[1] = 0u; }  // clear stale replay state
    gbar(tid);   // entry __syncthreads also covers the SMEM init

    // ---- main loop: layer0 A->B, gbar, layer1 B->A (+detect), gbar, check
    for (int it = 0; it < TT; it++) {
        const int par = it & 1;
        if (it > 0 && tid < 32) {
            float v = outdot_val(g_h[0], wvec, obias, bo, tid);
            if (tid == 0) out[obase + (it - 1)] = v;
        }
        do_layer<false>(0, g_h[0], g_h[1], sw, part, sbias, cta, tid, par);
        gbar(tid);
        do_layer<true >(1, g_h[1], g_h[0], sw, part, sbias, cta, tid, par);
        if (tid == 0) *(volatile unsigned*)&g_chg[(it + 1) & 1] = 0u;  // reset next slot
        gbar(tid);
        // Uniform early-exit decision: carry identical to previous step ->
        // every future carry/output is bitwise identical. Bulk-fill and quit.
        if (*(volatile unsigned*)&g_chg[par] == 0u) {
            if (tid < 32) {
                float v = outdot_val(g_h[0], wvec, obias, bo, tid);
                long long start = obase + (it > 0 ? it - 1 : 0);
                long long end   = obase + TT;
                for (long long i = start + tid; i < end; i += 32) out[i] = v;
            }
            return;
        }
    }
    // final step's outputs (no convergence)
    if (tid < 32) {
        float v = outdot_val(g_h[0], wvec, obias, bo, tid);
        if (tid == 0) out[obase + (TT - 1)] = v;
    }
}

extern "C" void kernel_launch(void* const* d_in, const int* in_sizes, int n_in,
                              void* d_out, int out_size) {
    (void)in_sizes; (void)n_in; (void)out_size;
    const float* u0   = (const float*)d_in[0];
    const float* w0   = (const float*)d_in[1];
    const float* Kc   = (const float*)d_in[2];
    const float* W_in = (const float*)d_in[3];
    const float* b_in = (const float*)d_in[4];
    const float* Wih0 = (const float*)d_in[5];
    // d_in[6] = W_hh0 (dead)
    const float* bih0 = (const float*)d_in[7];
    const float* bhh0 = (const float*)d_in[8];
    const float* Wih1 = (const float*)d_in[9];
    // d_in[10] = W_hh1 (dead)
    const float* bih1 = (const float*)d_in[11];
    const float* bhh1 = (const float*)d_in[12];
    const float* Wu   = (const float*)d_in[13];
    const float* bu   = (const float*)d_in[14];
    const float* Ww   = (const float*)d_in[15];
    const float* bw   = (const float*)d_in[16];
    float* out = (float*)d_out;

    cudaFuncSetAttribute(fhn_lstm_kernel,
                         cudaFuncAttributeMaxDynamicSharedMemorySize, SMEM_BYTES);
    fhn_lstm_kernel<<<NCTA, NTH, SMEM_BYTES>>>(
        u0, w0, Kc, W_in, b_in, Wih0, bih0, bhh0, Wih1, bih1, bhh1,
        Wu, bu, Ww, bw, out);
}

// round 8
// speedup vs baseline: 1.1906x; 1.1906x over previous
#include <cuda_runtime.h>
#include <cuda_bf16.h>

// ---------------------------------------------------------------------------
// FHN_LSTM: iterated two-layer "LSTM-from-zero" map.
//   B=64 batch, H=512 hidden, T=1000 steps.
//   Live gates only: i, g, o (f-gate and W_hh are dead since h0=c0=0).
//   h_next[d] = sig(o_d) * tanh( sig(i_d) * tanh(g_d) )
//   Outputs per step: u[b] = h.W_u + b_u, w[b] = h.W_w + b_w
//
// Persistent kernel: 128 CTAs x 512 threads (16 warps -> 4/SMSP for latency
// hiding; R6 profile showed issue=22% with only 2/SMSP). Each CTA owns 4
// h-dims, weights SMEM-resident. Grid barrier between layers.
// ---------------------------------------------------------------------------

#define NCTA   128
#define NTH    512
#define BB     64      // batch
#define HH     512     // hidden
#define TT     1000    // time steps
#define KP     256     // k-pairs (HH/2)
#define ROWS   12      // 3 gates * 4 dims per CTA per layer
#define KG     16      // k-groups (warps) in GEMM phase

// SMEM layout (floats)
#define SW_OFF    0                        // [2][12][512] weights
#define SW_SZ     (2 * ROWS * HH)          // 12288
#define PART_OFF  (SW_OFF + SW_SZ)         // [12][16][64] partials
#define PART_SZ   (ROWS * KG * BB)         // 12288
#define WV_OFF    (PART_OFF + PART_SZ)     // [512] output weight vector
#define WV_SZ     HH
#define BIAS_OFF  (WV_OFF + WV_SZ)         // [24] gate biases
#define BIAS_SZ   (2 * ROWS)
#define SMEM_FLOATS (BIAS_OFF + BIAS_SZ)
#define SMEM_BYTES  (SMEM_FLOATS * 4)

// Ping-pong h buffers. Layout: [kp][b] float2 = (h[2kp][b], h[2kp+1][b]).
__device__ __align__(16) float2 g_h[2][KP * BB];
__device__ unsigned g_bar;   // monotone ticket; 2^32 % NCTA == 0 -> wrap-safe

typedef unsigned long long ull;

__device__ __forceinline__ void ffma2(ull& d, ull a, ull b) {
    // packed 2x fp32 fma: d.lo += a.lo*b.lo ; d.hi += a.hi*b.hi
    asm("fma.rn.f32x2 %0, %1, %2, %0;" : "+l"(d) : "l"(a), "l"(b));
}
__device__ __forceinline__ float fold2(ull v) {
    return __uint_as_float((unsigned)v) + __uint_as_float((unsigned)(v >> 32));
}
__device__ __forceinline__ float sig_(float x) {
    return 1.0f / (1.0f + __expf(-x));
}
__device__ __forceinline__ float tanh_(float x) {
    return 1.0f - __fdividef(2.0f, __expf(2.0f * x) + 1.0f);
}

// Grid barrier. __threadfence() is gpu scope (>= cluster) so ptxas emits
// CCTL.IVALL, invalidating stale L1 lines of peer-written h buffers.
__device__ __forceinline__ void gbar(int tid) {
    __syncthreads();
    if (tid == 0) {
        __threadfence();
        unsigned pos    = atomicAdd(&g_bar, 1u);
        unsigned target = (pos - (pos & (NCTA - 1u))) + NCTA;
        while ((int)(*(volatile unsigned*)&g_bar - target) < 0) { }
        __threadfence();
    }
    __syncthreads();
}

// One dense layer for this CTA's 4 dims, all 64 batches.
// GEMM phase: kg = tid>>5 (warp = k-group of 32 k = 16 kp), bq = tid&31
// (lane = batch pair 2bq, 2bq+1). 8 iterations of 2 kp each; weights come
// as LDS.128 (two packed k-pairs per row).
__device__ __forceinline__ void do_layer(
    int l, const float2* __restrict__ inbuf, float2* __restrict__ outbuf,
    const float* sw, float* part, const float* sbias, int cta, int tid)
{
    const int kg = tid >> 5;
    const int bq = tid & 31;

    ull acc[ROWS][2];
#pragma unroll
    for (int r = 0; r < ROWS; r++) { acc[r][0] = 0ull; acc[r][1] = 0ull; }

    // ulonglong2 element (kp*32 + bq): .x = packed h(2kp,2kp+1) for batch 2bq,
    // .y = same for batch 2bq+1.
    const ulonglong2* hp = (const ulonglong2*)inbuf + bq;
    const float*      wl = sw + l * (ROWS * HH);
    const int kp0 = kg * 16;

#pragma unroll 2
    for (int sp = 0; sp < 8; sp++) {
        const int kp = kp0 + 2 * sp;
        ulonglong2 h0 = hp[(size_t)kp * 32];
        ulonglong2 h1 = hp[(size_t)(kp + 1) * 32];
#pragma unroll
        for (int r = 0; r < ROWS; r++) {
            // LDS.128: w2.x = packed w(2kp,2kp+1), w2.y = packed w(2kp+2,2kp+3)
            ulonglong2 w2 = *(const ulonglong2*)(wl + r * HH + 2 * kp);
            ffma2(acc[r][0], w2.x, h0.x);
            ffma2(acc[r][1], w2.x, h0.y);
            ffma2(acc[r][0], w2.y, h1.x);
            ffma2(acc[r][1], w2.y, h1.y);
        }
    }

    // partials -> SMEM [row][kg][b] (float2 per batch pair: conflict-free)
    float2* p2 = (float2*)part;
#pragma unroll
    for (int r = 0; r < ROWS; r++) {
        p2[(r * KG + kg) * 32 + bq] = make_float2(fold2(acc[r][0]), fold2(acc[r][1]));
    }
    __syncthreads();

    // reduce over kg + activations: threads 0..255 as (j = tid>>6, b = tid&63)
    if (tid < 4 * BB) {
        const int j = tid >> 6;
        const int b = tid & 63;
        float g3[3];
#pragma unroll
        for (int r = 0; r < 3; r++) {
            const int row = r * 4 + j;
            float s = sbias[l * ROWS + row];
#pragma unroll
            for (int k2 = 0; k2 < KG; k2++) s += part[(row * KG + k2) * BB + b];
            g3[r] = s;
        }
        const float c = sig_(g3[0]) * tanh_(g3[1]);
        const float h = sig_(g3[2]) * tanh_(c);

        const int d = 4 * cta + j;
        float* po = (float*)&outbuf[(d >> 1) * BB + b];
        po[d & 1] = h;
    }
}

// Output projection: one length-512 dot per CTA (u for cta<64, w else), by
// warp 0 reading the carry buffer. Butterfly reduce -> all lanes hold the sum.
__device__ __forceinline__ float outdot_val(
    const float2* __restrict__ hA, const float* wvec, float bias,
    int bo, int lane)
{
    float acc = 0.0f;
    const float2* wv2 = (const float2*)wvec;
#pragma unroll
    for (int m = 0; m < 8; m++) {
        const int kp = lane + 32 * m;
        float2 w2 = wv2[kp];
        float2 h2 = hA[kp * BB + bo];
        acc += w2.x * h2.x + w2.y * h2.y;
    }
#pragma unroll
    for (int off = 16; off > 0; off >>= 1)
        acc += __shfl_xor_sync(0xffffffffu, acc, off);
    return acc + bias;
}

__global__ void __launch_bounds__(NTH, 1) fhn_lstm_kernel(
    const float* __restrict__ u0,   const float* __restrict__ w0,
    const float* __restrict__ Kc,   const float* __restrict__ W_in,
    const float* __restrict__ b_in,
    const float* __restrict__ Wih0, const float* __restrict__ bih0,
    const float* __restrict__ bhh0,
    const float* __restrict__ Wih1, const float* __restrict__ bih1,
    const float* __restrict__ bhh1,
    const float* __restrict__ Wu,   const float* __restrict__ bu,
    const float* __restrict__ Ww,   const float* __restrict__ bw,
    float* __restrict__ out)
{
    extern __shared__ float smem[];
    float* sw    = smem + SW_OFF;
    float* part  = smem + PART_OFF;
    float* wvec  = smem + WV_OFF;
    float* sbias = smem + BIAS_OFF;

    const int cta = blockIdx.x;
    const int tid = threadIdx.x;

    // ---- init: weights (rows i,g,o of this CTA's 4 dims, both layers) -> SMEM
    // gate row base in pytorch [4H, H] layout: i=0, f=1(dead), g=2, o=3
    for (int idx = tid; idx < 2 * ROWS * HH; idx += NTH) {
        const int row = idx >> 9;          // 0..23
        const int k   = idx & (HH - 1);
        const int l   = row >= ROWS;
        const int rr  = row - l * ROWS;    // 0..11
        const int r   = rr >> 2;           // gate index 0..2
        const int j   = rr & 3;            // local dim
        const int gate = (r == 0) ? 0 : (r == 1) ? 2 : 3;
        const float* Wih = l ? Wih1 : Wih0;
        sw[idx] = Wih[(size_t)(gate * HH + 4 * cta + j) * HH + k];
    }
    if (tid < 2 * ROWS) {
        const int row = tid;
        const int l   = row >= ROWS;
        const int rr  = row - l * ROWS;
        const int r   = rr >> 2;
        const int j   = rr & 3;
        const int gate = (r == 0) ? 0 : (r == 1) ? 2 : 3;
        const int src  = gate * HH + 4 * cta + j;
        sbias[row] = (l ? bih1[src] : bih0[src]) + (l ? bhh1[src] : bhh0[src]);
    }
    {
        const float* wv = (cta < BB) ? Wu : Ww;
        for (int i = tid; i < HH; i += NTH) wvec[i] = wv[i];
    }
    const float obias  = (cta < BB) ? bu[0] : bw[0];
    const int   bo     = cta & (BB - 1);
    const long long obase = (long long)((cta < BB) ? 0 : BB * TT) + (long long)bo * TT;

    // ---- prologue: x = [u0,w0,K] @ W_in.T + b_in  -> carry buffer g_h[0]
    if (tid < 4 * BB) {
        const int j = tid >> 6;
        const int b = tid & 63;
        const int d = 4 * cta + j;
        const float x = W_in[d * 3 + 0] * u0[b] + W_in[d * 3 + 1] * w0[b]
                      + W_in[d * 3 + 2] * Kc[b] + b_in[d];
        float* po = (float*)&g_h[0][(d >> 1) * BB + b];
        po[d & 1] = x;
    }
    gbar(tid);   // entry __syncthreads also covers the SMEM init

    // ---- main loop: layer0 A->B, gbar, layer1 B->A, gbar
    for (int it = 0; it < TT; it++) {
        if (it > 0 && tid < 32) {
            float v = outdot_val(g_h[0], wvec, obias, bo, tid);
            if (tid == 0) out[obase + (it - 1)] = v;
        }
        do_layer(0, g_h[0], g_h[1], sw, part, sbias, cta, tid);
        gbar(tid);
        do_layer(1, g_h[1], g_h[0], sw, part, sbias, cta, tid);
        gbar(tid);
    }
    // final step's outputs
    if (tid < 32) {
        float v = outdot_val(g_h[0], wvec, obias, bo, tid);
        if (tid == 0) out[obase + (TT - 1)] = v;
    }
}

extern "C" void kernel_launch(void* const* d_in, const int* in_sizes, int n_in,
                              void* d_out, int out_size) {
    (void)in_sizes; (void)n_in; (void)out_size;
    const float* u0   = (const float*)d_in[0];
    const float* w0   = (const float*)d_in[1];
    const float* Kc   = (const float*)d_in[2];
    const float* W_in = (const float*)d_in[3];
    const float* b_in = (const float*)d_in[4];
    const float* Wih0 = (const float*)d_in[5];
    // d_in[6] = W_hh0 (dead)
    const float* bih0 = (const float*)d_in[7];
    const float* bhh0 = (const float*)d_in[8];
    const float* Wih1 = (const float*)d_in[9];
    // d_in[10] = W_hh1 (dead)
    const float* bih1 = (const float*)d_in[11];
    const float* bhh1 = (const float*)d_in[12];
    const float* Wu   = (const float*)d_in[13];
    const float* bu   = (const float*)d_in[14];
    const float* Ww   = (const float*)d_in[15];
    const float* bw   = (const float*)d_in[16];
    float* out = (float*)d_out;

    cudaFuncSetAttribute(fhn_lstm_kernel,
                         cudaFuncAttributeMaxDynamicSharedMemorySize, SMEM_BYTES);
    fhn_lstm_kernel<<<NCTA, NTH, SMEM_BYTES>>>(
        u0, w0, Kc, W_in, b_in, Wih0, bih0, bhh0, Wih1, bih1, bhh1,
        Wu, bu, Ww, bw, out);
}